// round 16
// baseline (speedup 1.0000x reference)
#include <cuda_runtime.h>
#include <cuda_bf16.h>
#include <math.h>

// ---------------------------------------------------------------------------
// B=8; input [8,3,256,256]; segmap [8,19,256,256]
// L1: conv 3->32 all-couts-per-block; two-pass IN after (R12)
// L2/L3: stride-2 conv tf32 mma, cp.async staging (R12)
// L4: convT tf32 mma per parity class, cp.async 2-buf (R12)
// L5: conv 256->512 + tanh + fused pooling, cp.async 2-buf,
//     halo channel-interleaved -> v2 B-frag loads (new)
// ---------------------------------------------------------------------------

#define NB 8
#define NS 19

__device__ float g_act1[NB * 32 * 256 * 256];
__device__ float g_act2[NB * 64 * 128 * 128];
__device__ float g_act3[NB * 128 * 64 * 64];
__device__ float g_act4[NB * 256 * 128 * 128];
__device__ int   g_label[NB * 128 * 128];
__device__ float g_sums[NB * NS * 512];
__device__ int   g_cnt[NB * NS];
// pre-converted, smem-layout weights (tf32 bits)
__device__ unsigned g_w2t[1 * 4 * 4608];          // [cog][cc][64co][72]
__device__ unsigned g_w3t[2 * 8 * 4608];
__device__ unsigned g_w5t[8 * 32 * 4608];
__device__ unsigned g_w4t[4 * 4 * 16 * 4 * 768];  // [cog][cls][cc][ta][64co][12]

__device__ __forceinline__ int refl(int v, int n) {
    return v < 0 ? -v : (v >= n ? 2 * n - 2 - v : v);
}

__device__ __forceinline__ unsigned f2tf(float f) {
    unsigned u;
    asm("cvt.rna.tf32.f32 %0, %1;" : "=r"(u) : "f"(f));
    return u;
}

__device__ __forceinline__ void mma_tf32(float* c, const unsigned* a, const unsigned* b) {
    asm volatile(
        "mma.sync.aligned.m16n8k8.row.col.f32.tf32.tf32.f32 "
        "{%0,%1,%2,%3}, {%4,%5,%6,%7}, {%8,%9}, {%0,%1,%2,%3};"
        : "+f"(c[0]), "+f"(c[1]), "+f"(c[2]), "+f"(c[3])
        : "r"(a[0]), "r"(a[1]), "r"(a[2]), "r"(a[3]), "r"(b[0]), "r"(b[1]));
}

__device__ __forceinline__ void cp_async4(unsigned dst, const void* src) {
    asm volatile("cp.async.ca.shared.global [%0], [%1], 4;" :: "r"(dst), "l"(src));
}
__device__ __forceinline__ void cp_async4_p(unsigned dst, const void* src, bool ok) {
    int sz = ok ? 4 : 0;
    asm volatile("cp.async.ca.shared.global [%0], [%1], 4, %2;"
                 :: "r"(dst), "l"(src), "r"(sz));
}
__device__ __forceinline__ void cp_async16(unsigned dst, const void* src) {
    asm volatile("cp.async.cg.shared.global [%0], [%1], 16;" :: "r"(dst), "l"(src));
}
#define CP_COMMIT() asm volatile("cp.async.commit_group;")
#define CP_WAIT1()  asm volatile("cp.async.wait_group 1;")
#define CP_WAIT0()  asm volatile("cp.async.wait_group 0;")

// ---------------------------------------------------------------------------
// merged init: zero accumulators + all weight prep in one launch
// ---------------------------------------------------------------------------
#define PREP_Z   (NB * NS * 512)
#define PREP_N2  (64 * 32 * 9)
#define PREP_N3  (128 * 64 * 9)
#define PREP_N5  (512 * 256 * 9)
#define PREP_N4  (4 * 4 * 16 * 4 * 768)
#define PREP_TOT (PREP_Z + PREP_N2 + PREP_N3 + PREP_N5 + PREP_N4)

__device__ __forceinline__ void prep_one(const float* src, unsigned* dst,
                                         int i, int cin) {
    int cog_co = i / (cin * 9);
    int r = i - cog_co * (cin * 9);
    int cc = r / 72, kk = r - cc * 72;
    int cog = cog_co >> 6, co = cog_co & 63;
    dst[((cog * (cin / 8) + cc) * 64 + co) * 72 + kk] = f2tf(src[i]);
}

__global__ void k_init_all(const float* __restrict__ w2, const float* __restrict__ w3,
                           const float* __restrict__ w5, const float* __restrict__ w4) {
    int i = blockIdx.x * 256 + threadIdx.x;
    if (i < PREP_Z) {
        g_sums[i] = 0.f;
        if (i < NB * NS) g_cnt[i] = 0;
        return;
    }
    i -= PREP_Z;
    if (i < PREP_N2) { prep_one(w2, g_w2t, i, 32); return; }
    i -= PREP_N2;
    if (i < PREP_N3) { prep_one(w3, g_w3t, i, 64); return; }
    i -= PREP_N3;
    if (i < PREP_N5) { prep_one(w5, g_w5t, i, 256); return; }
    i -= PREP_N5;
    if (i >= PREP_N4) return;
    {
        int q = i % 12;
        int t1 = i / 12;
        int co = t1 & 63;
        int t2 = t1 >> 6;
        int ta = t2 & 3;
        int t3 = t2 >> 2;
        int cc = t3 & 15;
        int t4 = t3 >> 4;
        int cls = t4 & 3;
        int cog = t4 >> 2;
        const int ntaps[4] = {1, 2, 2, 4};
        const int tvals[4][4] = {{4, 0, 0, 0}, {3, 5, 0, 0}, {1, 7, 0, 0}, {0, 2, 6, 8}};
        unsigned v = 0;
        if (q < 8 && ta < ntaps[cls]) {
            int tv = tvals[cls][ta];
            v = f2tf(w4[(((size_t)(cc * 8 + q)) * 256 + cog * 64 + co) * 9 + tv]);
        }
        g_w4t[i] = v;
    }
}

// ---------------------------------------------------------------------------
// conv1: reflect pad, 3->32. All 32 couts per block; input read once.
// ---------------------------------------------------------------------------
__global__ void k_conv1(const float* __restrict__ in, const float* __restrict__ w,
                        const float* __restrict__ bias) {
    int b = blockIdx.y;
    __shared__ float ws[864];
    __shared__ float bs[32];
    for (int i = threadIdx.x; i < 864; i += 256) ws[i] = w[i];
    if (threadIdx.x < 32) bs[threadIdx.x] = bias[threadIdx.x];
    __syncthreads();
    int idx = blockIdx.x * 256 + threadIdx.x;
    int y = idx >> 8, x = idx & 255;
    int ry[3], rx[3];
#pragma unroll
    for (int k = 0; k < 3; k++) { ry[k] = refl(y - 1 + k, 256); rx[k] = refl(x - 1 + k, 256); }
    float iv[27];
#pragma unroll
    for (int ci = 0; ci < 3; ci++) {
        const float* ip = in + ((size_t)(b * 3 + ci)) * 65536;
#pragma unroll
        for (int ky = 0; ky < 3; ky++) {
            const float* row = ip + ry[ky] * 256;
#pragma unroll
            for (int kx = 0; kx < 3; kx++)
                iv[ci * 9 + ky * 3 + kx] = row[rx[kx]];
        }
    }
    float* ob = g_act1 + (size_t)b * 32 * 65536 + idx;
#pragma unroll
    for (int co = 0; co < 32; co++) {
        float acc = bs[co];
        const float* wp = &ws[co * 27];
#pragma unroll
        for (int k = 0; k < 27; k++) acc = fmaf(iv[k], wp[k], acc);
        ob[(size_t)co * 65536] = acc;
    }
}

// ---------------------------------------------------------------------------
// fused instance-norm + leaky relu, float4, output pre-rounded to tf32
// ---------------------------------------------------------------------------
__global__ void k_in_lrelu(float* __restrict__ buf, int HW4) {
    float4* p = (float4*)(buf + (size_t)blockIdx.x * HW4 * 4);
    float s = 0.f, s2 = 0.f;
    for (int i = threadIdx.x; i < HW4; i += 256) {
        float4 v = p[i];
        s += v.x + v.y + v.z + v.w;
        s2 = fmaf(v.x, v.x, fmaf(v.y, v.y, fmaf(v.z, v.z, fmaf(v.w, v.w, s2))));
    }
#pragma unroll
    for (int o = 16; o; o >>= 1) {
        s  += __shfl_down_sync(0xffffffffu, s, o);
        s2 += __shfl_down_sync(0xffffffffu, s2, o);
    }
    __shared__ float sh[16];
    __shared__ float mr[2];
    int wid = threadIdx.x >> 5, lid = threadIdx.x & 31;
    if (lid == 0) { sh[wid] = s; sh[8 + wid] = s2; }
    __syncthreads();
    if (threadIdx.x == 0) {
        float ts = 0.f, t2 = 0.f;
        for (int j = 0; j < 8; j++) { ts += sh[j]; t2 += sh[8 + j]; }
        float inv = 1.0f / (float)(HW4 * 4);
        float m = ts * inv;
        float var = t2 * inv - m * m;
        mr[0] = m;
        mr[1] = rsqrtf(var + 1e-5f);
    }
    __syncthreads();
    float m = mr[0], r = mr[1];
    for (int i = threadIdx.x; i < HW4; i += 256) {
        float4 v = p[i];
        float a0 = (v.x - m) * r, a1 = (v.y - m) * r, a2 = (v.z - m) * r, a3 = (v.w - m) * r;
        a0 = a0 > 0.f ? a0 : 0.2f * a0;
        a1 = a1 > 0.f ? a1 : 0.2f * a1;
        a2 = a2 > 0.f ? a2 : 0.2f * a2;
        a3 = a3 > 0.f ? a3 : 0.2f * a3;
        float4 o;
        o.x = __uint_as_float(f2tf(a0));
        o.y = __uint_as_float(f2tf(a1));
        o.z = __uint_as_float(f2tf(a2));
        o.w = __uint_as_float(f2tf(a3));
        p[i] = o;
    }
}

// ---------------------------------------------------------------------------
// stride-2 conv via tf32 mma, cp.async staging (single buffer, static smem)
// grid: (COUT/64, tiles, NB)
// ---------------------------------------------------------------------------
template <int CIN, int HIN>
__global__ __launch_bounds__(128) void k_conv_s2_mma(const float* __restrict__ in,
                                                     const unsigned* __restrict__ wt,
                                                     const float* __restrict__ bias,
                                                     float* __restrict__ out,
                                                     int cout_total) {
    constexpr int HOUT = HIN / 2;
    constexpr int XTILES = HOUT / 16;
    constexpr int NCC = CIN / 8;
    const int b = blockIdx.z;
    const int cog = blockIdx.x;
    const int y0 = (blockIdx.y / XTILES) * 8;
    const int x0 = (blockIdx.y % XTILES) * 16;

    const int tid = threadIdx.x;
    const int lane = tid & 31;
    const int ww = tid >> 5;
    const int mwarp = ww & 1;
    const int nwarp = ww >> 1;
    const int gid = lane >> 2;
    const int tig = lane & 3;

    __shared__ unsigned s_in[8 * 569];
    __shared__ unsigned s_w[64 * 72];
    const unsigned i_sa = (unsigned)__cvta_generic_to_shared(s_in);
    const unsigned w_sa = (unsigned)__cvta_generic_to_shared(s_w);

    float acc[2][8][4];
#pragma unroll
    for (int mt = 0; mt < 2; mt++)
#pragma unroll
        for (int j = 0; j < 8; j++)
#pragma unroll
            for (int q = 0; q < 4; q++) acc[mt][j][q] = 0.f;

    const float* inb = in + (size_t)b * CIN * HIN * HIN;
    const int iy0 = 2 * y0 - 1, ix0 = 2 * x0 - 1;

    for (int cc = 0; cc < NCC; cc++) {
        __syncthreads();
        for (int idx = tid; idx < 8 * 561; idx += 128) {
            int c = idx / 561, r = idx - c * 561;
            int rr = r / 33, cx = r - rr * 33;
            int gy = iy0 + rr, gx = ix0 + cx;
            bool ok = ((unsigned)gy < (unsigned)HIN && (unsigned)gx < (unsigned)HIN);
            const float* src = ok ? &inb[((size_t)(cc * 8 + c) * HIN + gy) * HIN + gx] : inb;
            cp_async4_p(i_sa + (c * 569 + rr * 33 + cx) * 4, src, ok);
        }
        {
            const uint4* wsrc = (const uint4*)(wt + (size_t)(cog * NCC + cc) * 4608);
#pragma unroll
            for (int i = 0; i < 9; i++)
                cp_async16(w_sa + (tid + i * 128) * 16, wsrc + tid + i * 128);
        }
        CP_COMMIT();
        CP_WAIT0();
        __syncthreads();

#pragma unroll
        for (int t = 0; t < 9; t++) {
            const int ky = t / 3, kx = t - ky * 3;
            unsigned a[2][4];
#pragma unroll
            for (int mt = 0; mt < 2; mt++) {
                int mrow = mwarp * 32 + mt * 16 + gid;
                a[mt][0] = s_w[mrow * 72 + tig * 9 + t];
                a[mt][1] = s_w[(mrow + 8) * 72 + tig * 9 + t];
                a[mt][2] = s_w[mrow * 72 + (tig + 4) * 9 + t];
                a[mt][3] = s_w[(mrow + 8) * 72 + (tig + 4) * 9 + t];
            }
#pragma unroll
            for (int j = 0; j < 8; j++) {
                int jj = nwarp * 8 + j;
                int row = jj >> 1;
                int xcol = (jj & 1) * 8;
                int hy = 2 * row + ky;
                int hx = 2 * (xcol + gid) + kx;
                unsigned bf[2];
                bf[0] = s_in[tig * 569 + hy * 33 + hx];
                bf[1] = s_in[(tig + 4) * 569 + hy * 33 + hx];
                mma_tf32(acc[0][j], a[0], bf);
                mma_tf32(acc[1][j], a[1], bf);
            }
        }
    }

#pragma unroll
    for (int mt = 0; mt < 2; mt++) {
        int co0 = cog * 64 + mwarp * 32 + mt * 16 + gid;
        float bs0 = bias[co0];
        float bs1 = bias[co0 + 8];
#pragma unroll
        for (int j = 0; j < 8; j++) {
            int jj = nwarp * 8 + j;
            int y = y0 + (jj >> 1);
            int x = x0 + (jj & 1) * 8 + 2 * tig;
            float2 v0 = make_float2(acc[mt][j][0] + bs0, acc[mt][j][1] + bs0);
            float2 v1 = make_float2(acc[mt][j][2] + bs1, acc[mt][j][3] + bs1);
            *(float2*)&out[(((size_t)(b * cout_total + co0)) * HOUT + y) * HOUT + x] = v0;
            *(float2*)&out[(((size_t)(b * cout_total + co0 + 8)) * HOUT + y) * HOUT + x] = v1;
        }
    }
}

// ---------------------------------------------------------------------------
// convT via tf32 mma, per parity class, cp.async DOUBLE-buffered (static smem)
// grid: (16, 32, NB)
// ---------------------------------------------------------------------------
__global__ __launch_bounds__(128) void k_convT_mma(const float* __restrict__ in,
                                                   const float* __restrict__ bias,
                                                   float* __restrict__ out) {
    const int b = blockIdx.z;
    const int z = blockIdx.x;
    const int cog = z >> 2, cls = z & 3;
    const int py = cls >> 1, px = cls & 1;
    const int y0 = (blockIdx.y >> 2) * 8;
    const int x0 = (blockIdx.y & 3) * 16;

    const int tid = threadIdx.x;
    const int lane = tid & 31;
    const int ww = tid >> 5;
    const int mwarp = ww & 1;
    const int nwarp = ww >> 1;
    const int gid = lane >> 2;
    const int tig = lane & 3;

    int nky = py ? 2 : 1, nkx = px ? 2 : 1;
    int dyA[2] = {0, 0};
    if (py) { dyA[0] = 1; dyA[1] = 0; }
    int dxA[2] = {0, 0};
    if (px) { dxA[0] = 1; dxA[1] = 0; }
    const int ntaps = nky * nkx;
    int tdy[4], tdx[4];
    for (int a = 0; a < nky; a++)
        for (int e = 0; e < nkx; e++) {
            int ta = a * nkx + e;
            tdy[ta] = dyA[a];
            tdx[ta] = dxA[e];
        }

    __shared__ uint4 s_w4[2][768];
    __shared__ unsigned s_ibuf[2][1344];
    const unsigned w_sa = (unsigned)__cvta_generic_to_shared(s_w4);
    const unsigned i_sa = (unsigned)__cvta_generic_to_shared(s_ibuf);

    float acc[2][8][4];
#pragma unroll
    for (int mt = 0; mt < 2; mt++)
#pragma unroll
        for (int j = 0; j < 8; j++)
#pragma unroll
            for (int q = 0; q < 4; q++) acc[mt][j][q] = 0.f;

    const float* inb = in + (size_t)b * 128 * 4096;
    const int nw4 = ntaps * 192;

    auto stage = [&](int cc, int buf) {
        unsigned ib = i_sa + buf * 5376;
        for (int idx = tid; idx < 8 * 153; idx += 128) {
            int c = idx / 153, r = idx - c * 153;
            int rr = r / 17, cx = r - rr * 17;
            int gy = y0 + rr, gx = x0 + cx;
            bool ok = (gy < 64 && gx < 64);
            const float* src = ok ? &inb[((size_t)(cc * 8 + c) * 64 + gy) * 64 + gx] : inb;
            cp_async4_p(ib + (c * 168 + rr * 17 + cx) * 4, src, ok);
        }
        unsigned wb = w_sa + buf * 12288;
        const uint4* wsrc =
            (const uint4*)(g_w4t + (size_t)(((cog * 4 + cls) * 16 + cc) * 4) * 768);
        for (int i = tid; i < nw4; i += 128) cp_async16(wb + i * 16, wsrc + i);
    };

    stage(0, 0);
    CP_COMMIT();

    for (int cc = 0; cc < 16; cc++) {
        __syncthreads();
        if (cc + 1 < 16) {
            stage(cc + 1, (cc + 1) & 1);
            CP_COMMIT();
            CP_WAIT1();
        } else {
            CP_WAIT0();
        }
        __syncthreads();
        const unsigned* s_in = s_ibuf[cc & 1];
        const unsigned* s_w = (const unsigned*)s_w4[cc & 1];

        for (int ta = 0; ta < ntaps; ta++) {
            unsigned a[2][4];
#pragma unroll
            for (int mt = 0; mt < 2; mt++) {
                int mrow = mwarp * 32 + mt * 16 + gid;
                a[mt][0] = s_w[ta * 768 + mrow * 12 + tig];
                a[mt][1] = s_w[ta * 768 + (mrow + 8) * 12 + tig];
                a[mt][2] = s_w[ta * 768 + mrow * 12 + tig + 4];
                a[mt][3] = s_w[ta * 768 + (mrow + 8) * 12 + tig + 4];
            }
            int dy = tdy[ta], dx = tdx[ta];
#pragma unroll
            for (int j = 0; j < 8; j++) {
                int jj = nwarp * 8 + j;
                int hy = (jj >> 1) + dy;
                int hx = (jj & 1) * 8 + gid + dx;
                unsigned bf[2];
                bf[0] = s_in[tig * 168 + hy * 17 + hx];
                bf[1] = s_in[(tig + 4) * 168 + hy * 17 + hx];
                mma_tf32(acc[0][j], a[0], bf);
                mma_tf32(acc[1][j], a[1], bf);
            }
        }
    }

#pragma unroll
    for (int mt = 0; mt < 2; mt++) {
        int co0 = cog * 64 + mwarp * 32 + mt * 16 + gid;
        float bs0 = bias[co0];
        float bs1 = bias[co0 + 8];
#pragma unroll
        for (int j = 0; j < 8; j++) {
            int jj = nwarp * 8 + j;
            int yc = y0 + (jj >> 1);
            int xc = x0 + (jj & 1) * 8 + 2 * tig;
            int y = 2 * yc + py;
            int x = 2 * xc + px;
            size_t o0 = (((size_t)(b * 256 + co0)) * 128 + y) * 128 + x;
            size_t o1 = (((size_t)(b * 256 + co0 + 8)) * 128 + y) * 128 + x;
            out[o0] = acc[mt][j][0] + bs0;
            out[o0 + 2] = acc[mt][j][1] + bs0;
            out[o1] = acc[mt][j][2] + bs1;
            out[o1 + 2] = acc[mt][j][3] + bs1;
        }
    }
}

// ---------------------------------------------------------------------------
// conv5 via tf32 mma + fused pooling, cp.async double-buffered.
// Halo channel-INTERLEAVED: word (pos*8 + slot), slot = (c&3)*2 + (c>>2),
// so B-fragments (channels tig, tig+4) load as one ld.shared.v2.
// smem: w[2][4608] + halo[2][1440] = 48384 B. Pool overlays halo.
// grid (cog=8, tile=128, b=NB), 128 threads.
// ---------------------------------------------------------------------------
__global__ __launch_bounds__(128) void k_conv5_mma(const float* __restrict__ in,
                                                   const float* __restrict__ bias) {
    const int b = blockIdx.z;
    const int cog = blockIdx.x;
    const int y0 = (blockIdx.y >> 3) * 8;
    const int x0 = (blockIdx.y & 7) * 16;

    const int tid = threadIdx.x;
    const int lane = tid & 31;
    const int ww = tid >> 5;
    const int mwarp = ww & 1;
    const int nwarp = ww >> 1;
    const int gid = lane >> 2;
    const int tig = lane & 3;

    __shared__ __align__(16) unsigned s_raw[2 * 4608 + 2 * 1440];
    unsigned* s_wb = s_raw;
    unsigned* s_ib = s_raw + 9216;
    const unsigned base_sa = (unsigned)__cvta_generic_to_shared(s_raw);
    const unsigned w_sa = base_sa;
    const unsigned i_sa = base_sa + 9216 * 4;

    float acc[2][8][4];
#pragma unroll
    for (int mt = 0; mt < 2; mt++)
#pragma unroll
        for (int j = 0; j < 8; j++)
#pragma unroll
            for (int q = 0; q < 4; q++) acc[mt][j][q] = 0.f;

    const float* inb = in + (size_t)b * 256 * 16384;
    const int warp4 = tid >> 5;
    const int ln = tid & 31;

    auto stage = [&](int cc, int buf) {
        unsigned ib = i_sa + buf * 5760;
        const float* cbase = inb + (size_t)cc * 8 * 16384;
        // warp-per-channel: coalesced global reads, interleaved smem writes
        for (int ci = warp4; ci < 8; ci += 4) {
            int slot = (ci & 3) * 2 + (ci >> 2);
            const float* cpl = cbase + ci * 16384;
            for (int pos = ln; pos < 180; pos += 32) {
                int yy = pos / 18, xx = pos - yy * 18;
                int gy = refl(y0 - 1 + yy, 128);
                int gx = refl(x0 - 1 + xx, 128);
                cp_async4(ib + (pos * 8 + slot) * 4, cpl + gy * 128 + gx);
            }
        }
        unsigned wb = w_sa + buf * 18432;
        const uint4* wsrc = (const uint4*)(g_w5t + (size_t)(cog * 32 + cc) * 4608);
#pragma unroll
        for (int i = 0; i < 9; i++)
            cp_async16(wb + (tid + i * 128) * 16, wsrc + tid + i * 128);
    };

    stage(0, 0);
    CP_COMMIT();

    for (int cc = 0; cc < 32; cc++) {
        __syncthreads();
        if (cc + 1 < 32) {
            stage(cc + 1, (cc + 1) & 1);
            CP_COMMIT();
            CP_WAIT1();
        } else {
            CP_WAIT0();
        }
        __syncthreads();
        const unsigned* s_in = s_ib + (cc & 1) * 1440;
        const unsigned* s_w = s_wb + (cc & 1) * 4608;

#pragma unroll
        for (int t = 0; t < 9; t++) {
            const int ky = t / 3, kx = t - ky * 3;
            unsigned a[2][4];
#pragma unroll
            for (int mt = 0; mt < 2; mt++) {
                int mrow = mwarp * 32 + mt * 16 + gid;
                a[mt][0] = s_w[mrow * 72 + tig * 9 + t];
                a[mt][1] = s_w[(mrow + 8) * 72 + tig * 9 + t];
                a[mt][2] = s_w[mrow * 72 + (tig + 4) * 9 + t];
                a[mt][3] = s_w[(mrow + 8) * 72 + (tig + 4) * 9 + t];
            }
            unsigned bcur[2], bnxt[2];
            {
                int jj = nwarp * 8;
                int hy = (jj >> 1) + ky;
                int hx = (jj & 1) * 8 + gid + kx;
                uint2 bv = *(const uint2*)&s_in[(hy * 18 + hx) * 8 + tig * 2];
                bcur[0] = bv.x;
                bcur[1] = bv.y;
            }
#pragma unroll
            for (int j = 0; j < 8; j++) {
                if (j < 7) {
                    int jj = nwarp * 8 + j + 1;
                    int hy = (jj >> 1) + ky;
                    int hx = (jj & 1) * 8 + gid + kx;
                    uint2 bv = *(const uint2*)&s_in[(hy * 18 + hx) * 8 + tig * 2];
                    bnxt[0] = bv.x;
                    bnxt[1] = bv.y;
                }
                mma_tf32(acc[0][j], a[0], bcur);
                mma_tf32(acc[1][j], a[1], bcur);
                bcur[0] = bnxt[0];
                bcur[1] = bnxt[1];
            }
        }
    }

    // epilogue: pool bins overlay dead halo buffers
    __syncthreads();
    float* s_pool = (float*)(s_raw + 9216);
    for (int i = tid; i < NS * 65; i += 128) s_pool[i] = 0.f;
    __syncthreads();

    const int* labp = g_label + b * 16384;
#pragma unroll
    for (int j = 0; j < 8; j++) {
        int jj = nwarp * 8 + j;
        int ly = jj >> 1;
        int lx = (jj & 1) * 8 + 2 * tig;
        int lbase = (y0 + ly) * 128 + x0 + lx;
        int lab0 = labp[lbase];
        int lab1 = labp[lbase + 1];
#pragma unroll
        for (int mt = 0; mt < 2; mt++) {
            int cl0 = mwarp * 32 + mt * 16 + gid;
            int co0 = cog * 64 + cl0;
            float bs0 = bias[co0];
            float bs1 = bias[co0 + 8];
            float v00 = tanhf(acc[mt][j][0] + bs0);
            float v01 = tanhf(acc[mt][j][1] + bs0);
            float v10 = tanhf(acc[mt][j][2] + bs1);
            float v11 = tanhf(acc[mt][j][3] + bs1);
            atomicAdd(&s_pool[lab0 * 65 + cl0], v00);
            atomicAdd(&s_pool[lab1 * 65 + cl0], v01);
            atomicAdd(&s_pool[lab0 * 65 + cl0 + 8], v10);
            atomicAdd(&s_pool[lab1 * 65 + cl0 + 8], v11);
        }
    }
    __syncthreads();
    for (int i = tid; i < NS * 64; i += 128) {
        int s = i >> 6, co = i & 63;
        float v = s_pool[s * 65 + co];
        if (v != 0.f)
            atomicAdd(&g_sums[((size_t)b * NS + s) * 512 + cog * 64 + co], v);
    }
}

// ---------------------------------------------------------------------------
__global__ void k_label(const float* __restrict__ seg) {
    int b = blockIdx.y;
    int i = blockIdx.x * 256 + threadIdx.x;
    int h = i >> 7, wv = i & 127;
    const float* sp = seg + (size_t)b * NS * 65536 + (2 * h) * 256 + 2 * wv;
    int lab = 0;
#pragma unroll 1
    for (int s = 0; s < NS; s++) {
        float v = sp[(size_t)s * 65536];
        if (v > 0.f) lab = s;
    }
    g_label[b * 16384 + i] = lab;
    atomicAdd(&g_cnt[b * NS + lab], 1);
}

// ---------------------------------------------------------------------------
__global__ void k_final(float* __restrict__ out) {
    int idx = blockIdx.x * 256 + threadIdx.x;
    if (idx >= NB * NS * 512) return;
    int bs = idx >> 9;
    int cnt = g_cnt[bs];
    out[idx] = cnt > 0 ? g_sums[idx] / (float)cnt : 0.f;
}

// ---------------------------------------------------------------------------
extern "C" void kernel_launch(void* const* d_in, const int* in_sizes, int n_in,
                              void* d_out, int out_size) {
    const float* input  = (const float*)d_in[0];
    const float* segmap = (const float*)d_in[1];
    const float* w1 = (const float*)d_in[2];
    const float* b1 = (const float*)d_in[3];
    const float* w2 = (const float*)d_in[4];
    const float* b2 = (const float*)d_in[5];
    const float* w3 = (const float*)d_in[6];
    const float* b3 = (const float*)d_in[7];
    const float* w4 = (const float*)d_in[8];
    const float* b4 = (const float*)d_in[9];
    const float* w5 = (const float*)d_in[10];
    const float* b5 = (const float*)d_in[11];
    float* out = (float*)d_out;

    float* act1;  cudaGetSymbolAddress((void**)&act1, g_act1);
    float* act2;  cudaGetSymbolAddress((void**)&act2, g_act2);
    float* act3;  cudaGetSymbolAddress((void**)&act3, g_act3);
    float* act4;  cudaGetSymbolAddress((void**)&act4, g_act4);
    unsigned* w2t; cudaGetSymbolAddress((void**)&w2t, g_w2t);
    unsigned* w3t; cudaGetSymbolAddress((void**)&w3t, g_w3t);

    // init + all weight prep in one launch
    k_init_all<<<(PREP_TOT + 255) / 256, 256>>>(w2, w3, w5, w4);
    k_label<<<dim3(64, NB), 256>>>(segmap);

    // L1
    k_conv1<<<dim3(256, NB), 256>>>(input, w1, b1);
    k_in_lrelu<<<NB * 32, 256>>>(act1, 65536 / 4);
    // L2
    k_conv_s2_mma<32, 256><<<dim3(1, 128, NB), 128>>>(act1, w2t, b2, act2, 64);
    k_in_lrelu<<<NB * 64, 256>>>(act2, 16384 / 4);
    // L3
    k_conv_s2_mma<64, 128><<<dim3(2, 32, NB), 128>>>(act2, w3t, b3, act3, 128);
    k_in_lrelu<<<NB * 128, 256>>>(act3, 4096 / 4);
    // L4
    k_convT_mma<<<dim3(16, 32, NB), 128>>>(act3, b4, act4);
    k_in_lrelu<<<NB * 256, 256>>>(act4, 16384 / 4);
    // L5 + fused pooling (interleaved halo, v2 B-frags)
    k_conv5_mma<<<dim3(8, 128, NB), 128>>>(act4, b5);
    // finalize
    k_final<<<(NB * NS * 512 + 255) / 256, 256>>>(out);
}

// round 17
// speedup vs baseline: 1.0523x; 1.0523x over previous
#include <cuda_runtime.h>
#include <cuda_bf16.h>
#include <math.h>

// ---------------------------------------------------------------------------
// B=8; input [8,3,256,256]; segmap [8,19,256,256]
// L1: conv 3->32 all-couts-per-block (input read once); two-pass IN after
// L2/L3: stride-2 conv tf32 mma, cp.async staging (static smem)
// L4: convT tf32 mma per parity class, cp.async double-buffered
// L5: conv 256->512 + tanh + fused pooling, cp.async DOUBLE-buffered (48.6KB)
// (exact R12 kernel bodies; init+weight-prep merged into one launch)
// ---------------------------------------------------------------------------

#define NB 8
#define NS 19

__device__ float g_act1[NB * 32 * 256 * 256];
__device__ float g_act2[NB * 64 * 128 * 128];
__device__ float g_act3[NB * 128 * 64 * 64];
__device__ float g_act4[NB * 256 * 128 * 128];
__device__ int   g_label[NB * 128 * 128];
__device__ float g_sums[NB * NS * 512];
__device__ int   g_cnt[NB * NS];
// pre-converted, smem-layout weights (tf32 bits)
__device__ unsigned g_w2t[1 * 4 * 4608];          // [cog][cc][64co][72]
__device__ unsigned g_w3t[2 * 8 * 4608];
__device__ unsigned g_w5t[8 * 32 * 4608];
__device__ unsigned g_w4t[4 * 4 * 16 * 4 * 768];  // [cog][cls][cc][ta][64co][12]

__device__ __forceinline__ int refl(int v, int n) {
    return v < 0 ? -v : (v >= n ? 2 * n - 2 - v : v);
}

__device__ __forceinline__ unsigned f2tf(float f) {
    unsigned u;
    asm("cvt.rna.tf32.f32 %0, %1;" : "=r"(u) : "f"(f));
    return u;
}

__device__ __forceinline__ void mma_tf32(float* c, const unsigned* a, const unsigned* b) {
    asm volatile(
        "mma.sync.aligned.m16n8k8.row.col.f32.tf32.tf32.f32 "
        "{%0,%1,%2,%3}, {%4,%5,%6,%7}, {%8,%9}, {%0,%1,%2,%3};"
        : "+f"(c[0]), "+f"(c[1]), "+f"(c[2]), "+f"(c[3])
        : "r"(a[0]), "r"(a[1]), "r"(a[2]), "r"(a[3]), "r"(b[0]), "r"(b[1]));
}

__device__ __forceinline__ void cp_async4(unsigned dst, const void* src) {
    asm volatile("cp.async.ca.shared.global [%0], [%1], 4;" :: "r"(dst), "l"(src));
}
__device__ __forceinline__ void cp_async4_p(unsigned dst, const void* src, bool ok) {
    int sz = ok ? 4 : 0;
    asm volatile("cp.async.ca.shared.global [%0], [%1], 4, %2;"
                 :: "r"(dst), "l"(src), "r"(sz));
}
__device__ __forceinline__ void cp_async16(unsigned dst, const void* src) {
    asm volatile("cp.async.cg.shared.global [%0], [%1], 16;" :: "r"(dst), "l"(src));
}
#define CP_COMMIT() asm volatile("cp.async.commit_group;")
#define CP_WAIT1()  asm volatile("cp.async.wait_group 1;")
#define CP_WAIT0()  asm volatile("cp.async.wait_group 0;")

// ---------------------------------------------------------------------------
// merged init: zero accumulators + all weight prep in one launch
// ---------------------------------------------------------------------------
#define PREP_Z   (NB * NS * 512)
#define PREP_N2  (64 * 32 * 9)
#define PREP_N3  (128 * 64 * 9)
#define PREP_N5  (512 * 256 * 9)
#define PREP_N4  (4 * 4 * 16 * 4 * 768)
#define PREP_TOT (PREP_Z + PREP_N2 + PREP_N3 + PREP_N5 + PREP_N4)

__device__ __forceinline__ void prep_one(const float* src, unsigned* dst,
                                         int i, int cin) {
    int cog_co = i / (cin * 9);
    int r = i - cog_co * (cin * 9);
    int cc = r / 72, kk = r - cc * 72;
    int cog = cog_co >> 6, co = cog_co & 63;
    dst[((cog * (cin / 8) + cc) * 64 + co) * 72 + kk] = f2tf(src[i]);
}

__global__ void k_init_all(const float* __restrict__ w2, const float* __restrict__ w3,
                           const float* __restrict__ w5, const float* __restrict__ w4) {
    int i = blockIdx.x * 256 + threadIdx.x;
    if (i < PREP_Z) {
        g_sums[i] = 0.f;
        if (i < NB * NS) g_cnt[i] = 0;
        return;
    }
    i -= PREP_Z;
    if (i < PREP_N2) { prep_one(w2, g_w2t, i, 32); return; }
    i -= PREP_N2;
    if (i < PREP_N3) { prep_one(w3, g_w3t, i, 64); return; }
    i -= PREP_N3;
    if (i < PREP_N5) { prep_one(w5, g_w5t, i, 256); return; }
    i -= PREP_N5;
    if (i >= PREP_N4) return;
    {
        int q = i % 12;
        int t1 = i / 12;
        int co = t1 & 63;
        int t2 = t1 >> 6;
        int ta = t2 & 3;
        int t3 = t2 >> 2;
        int cc = t3 & 15;
        int t4 = t3 >> 4;
        int cls = t4 & 3;
        int cog = t4 >> 2;
        const int ntaps[4] = {1, 2, 2, 4};
        const int tvals[4][4] = {{4, 0, 0, 0}, {3, 5, 0, 0}, {1, 7, 0, 0}, {0, 2, 6, 8}};
        unsigned v = 0;
        if (q < 8 && ta < ntaps[cls]) {
            int tv = tvals[cls][ta];
            v = f2tf(w4[(((size_t)(cc * 8 + q)) * 256 + cog * 64 + co) * 9 + tv]);
        }
        g_w4t[i] = v;
    }
}

// ---------------------------------------------------------------------------
// conv1: reflect pad, 3->32. All 32 couts per block; input read once.
// ---------------------------------------------------------------------------
__global__ void k_conv1(const float* __restrict__ in, const float* __restrict__ w,
                        const float* __restrict__ bias) {
    int b = blockIdx.y;
    __shared__ float ws[864];
    __shared__ float bs[32];
    for (int i = threadIdx.x; i < 864; i += 256) ws[i] = w[i];
    if (threadIdx.x < 32) bs[threadIdx.x] = bias[threadIdx.x];
    __syncthreads();
    int idx = blockIdx.x * 256 + threadIdx.x;
    int y = idx >> 8, x = idx & 255;
    int ry[3], rx[3];
#pragma unroll
    for (int k = 0; k < 3; k++) { ry[k] = refl(y - 1 + k, 256); rx[k] = refl(x - 1 + k, 256); }
    float iv[27];
#pragma unroll
    for (int ci = 0; ci < 3; ci++) {
        const float* ip = in + ((size_t)(b * 3 + ci)) * 65536;
#pragma unroll
        for (int ky = 0; ky < 3; ky++) {
            const float* row = ip + ry[ky] * 256;
#pragma unroll
            for (int kx = 0; kx < 3; kx++)
                iv[ci * 9 + ky * 3 + kx] = row[rx[kx]];
        }
    }
    float* ob = g_act1 + (size_t)b * 32 * 65536 + idx;
#pragma unroll
    for (int co = 0; co < 32; co++) {
        float acc = bs[co];
        const float* wp = &ws[co * 27];
#pragma unroll
        for (int k = 0; k < 27; k++) acc = fmaf(iv[k], wp[k], acc);
        ob[(size_t)co * 65536] = acc;
    }
}

// ---------------------------------------------------------------------------
// fused instance-norm + leaky relu, float4, output pre-rounded to tf32
// ---------------------------------------------------------------------------
__global__ void k_in_lrelu(float* __restrict__ buf, int HW4) {
    float4* p = (float4*)(buf + (size_t)blockIdx.x * HW4 * 4);
    float s = 0.f, s2 = 0.f;
    for (int i = threadIdx.x; i < HW4; i += 256) {
        float4 v = p[i];
        s += v.x + v.y + v.z + v.w;
        s2 = fmaf(v.x, v.x, fmaf(v.y, v.y, fmaf(v.z, v.z, fmaf(v.w, v.w, s2))));
    }
#pragma unroll
    for (int o = 16; o; o >>= 1) {
        s  += __shfl_down_sync(0xffffffffu, s, o);
        s2 += __shfl_down_sync(0xffffffffu, s2, o);
    }
    __shared__ float sh[16];
    __shared__ float mr[2];
    int wid = threadIdx.x >> 5, lid = threadIdx.x & 31;
    if (lid == 0) { sh[wid] = s; sh[8 + wid] = s2; }
    __syncthreads();
    if (threadIdx.x == 0) {
        float ts = 0.f, t2 = 0.f;
        for (int j = 0; j < 8; j++) { ts += sh[j]; t2 += sh[8 + j]; }
        float inv = 1.0f / (float)(HW4 * 4);
        float m = ts * inv;
        float var = t2 * inv - m * m;
        mr[0] = m;
        mr[1] = rsqrtf(var + 1e-5f);
    }
    __syncthreads();
    float m = mr[0], r = mr[1];
    for (int i = threadIdx.x; i < HW4; i += 256) {
        float4 v = p[i];
        float a0 = (v.x - m) * r, a1 = (v.y - m) * r, a2 = (v.z - m) * r, a3 = (v.w - m) * r;
        a0 = a0 > 0.f ? a0 : 0.2f * a0;
        a1 = a1 > 0.f ? a1 : 0.2f * a1;
        a2 = a2 > 0.f ? a2 : 0.2f * a2;
        a3 = a3 > 0.f ? a3 : 0.2f * a3;
        float4 o;
        o.x = __uint_as_float(f2tf(a0));
        o.y = __uint_as_float(f2tf(a1));
        o.z = __uint_as_float(f2tf(a2));
        o.w = __uint_as_float(f2tf(a3));
        p[i] = o;
    }
}

// ---------------------------------------------------------------------------
// stride-2 conv via tf32 mma, cp.async staging (single buffer, static smem)
// grid: (COUT/64, tiles, NB)
// ---------------------------------------------------------------------------
template <int CIN, int HIN>
__global__ __launch_bounds__(128) void k_conv_s2_mma(const float* __restrict__ in,
                                                     const unsigned* __restrict__ wt,
                                                     const float* __restrict__ bias,
                                                     float* __restrict__ out,
                                                     int cout_total) {
    constexpr int HOUT = HIN / 2;
    constexpr int XTILES = HOUT / 16;
    constexpr int NCC = CIN / 8;
    const int b = blockIdx.z;
    const int cog = blockIdx.x;
    const int y0 = (blockIdx.y / XTILES) * 8;
    const int x0 = (blockIdx.y % XTILES) * 16;

    const int tid = threadIdx.x;
    const int lane = tid & 31;
    const int ww = tid >> 5;
    const int mwarp = ww & 1;
    const int nwarp = ww >> 1;
    const int gid = lane >> 2;
    const int tig = lane & 3;

    __shared__ unsigned s_in[8 * 569];
    __shared__ unsigned s_w[64 * 72];
    const unsigned i_sa = (unsigned)__cvta_generic_to_shared(s_in);
    const unsigned w_sa = (unsigned)__cvta_generic_to_shared(s_w);

    float acc[2][8][4];
#pragma unroll
    for (int mt = 0; mt < 2; mt++)
#pragma unroll
        for (int j = 0; j < 8; j++)
#pragma unroll
            for (int q = 0; q < 4; q++) acc[mt][j][q] = 0.f;

    const float* inb = in + (size_t)b * CIN * HIN * HIN;
    const int iy0 = 2 * y0 - 1, ix0 = 2 * x0 - 1;

    for (int cc = 0; cc < NCC; cc++) {
        __syncthreads();
        for (int idx = tid; idx < 8 * 561; idx += 128) {
            int c = idx / 561, r = idx - c * 561;
            int rr = r / 33, cx = r - rr * 33;
            int gy = iy0 + rr, gx = ix0 + cx;
            bool ok = ((unsigned)gy < (unsigned)HIN && (unsigned)gx < (unsigned)HIN);
            const float* src = ok ? &inb[((size_t)(cc * 8 + c) * HIN + gy) * HIN + gx] : inb;
            cp_async4_p(i_sa + (c * 569 + rr * 33 + cx) * 4, src, ok);
        }
        {
            const uint4* wsrc = (const uint4*)(wt + (size_t)(cog * NCC + cc) * 4608);
#pragma unroll
            for (int i = 0; i < 9; i++)
                cp_async16(w_sa + (tid + i * 128) * 16, wsrc + tid + i * 128);
        }
        CP_COMMIT();
        CP_WAIT0();
        __syncthreads();

#pragma unroll
        for (int t = 0; t < 9; t++) {
            const int ky = t / 3, kx = t - ky * 3;
            unsigned a[2][4];
#pragma unroll
            for (int mt = 0; mt < 2; mt++) {
                int mrow = mwarp * 32 + mt * 16 + gid;
                a[mt][0] = s_w[mrow * 72 + tig * 9 + t];
                a[mt][1] = s_w[(mrow + 8) * 72 + tig * 9 + t];
                a[mt][2] = s_w[mrow * 72 + (tig + 4) * 9 + t];
                a[mt][3] = s_w[(mrow + 8) * 72 + (tig + 4) * 9 + t];
            }
#pragma unroll
            for (int j = 0; j < 8; j++) {
                int jj = nwarp * 8 + j;
                int row = jj >> 1;
                int xcol = (jj & 1) * 8;
                int hy = 2 * row + ky;
                int hx = 2 * (xcol + gid) + kx;
                unsigned bf[2];
                bf[0] = s_in[tig * 569 + hy * 33 + hx];
                bf[1] = s_in[(tig + 4) * 569 + hy * 33 + hx];
                mma_tf32(acc[0][j], a[0], bf);
                mma_tf32(acc[1][j], a[1], bf);
            }
        }
    }

#pragma unroll
    for (int mt = 0; mt < 2; mt++) {
        int co0 = cog * 64 + mwarp * 32 + mt * 16 + gid;
        float bs0 = bias[co0];
        float bs1 = bias[co0 + 8];
#pragma unroll
        for (int j = 0; j < 8; j++) {
            int jj = nwarp * 8 + j;
            int y = y0 + (jj >> 1);
            int x = x0 + (jj & 1) * 8 + 2 * tig;
            float2 v0 = make_float2(acc[mt][j][0] + bs0, acc[mt][j][1] + bs0);
            float2 v1 = make_float2(acc[mt][j][2] + bs1, acc[mt][j][3] + bs1);
            *(float2*)&out[(((size_t)(b * cout_total + co0)) * HOUT + y) * HOUT + x] = v0;
            *(float2*)&out[(((size_t)(b * cout_total + co0 + 8)) * HOUT + y) * HOUT + x] = v1;
        }
    }
}

// ---------------------------------------------------------------------------
// convT via tf32 mma, per parity class, cp.async DOUBLE-buffered (static smem)
// grid: (16, 32, NB)
// ---------------------------------------------------------------------------
__global__ __launch_bounds__(128) void k_convT_mma(const float* __restrict__ in,
                                                   const float* __restrict__ bias,
                                                   float* __restrict__ out) {
    const int b = blockIdx.z;
    const int z = blockIdx.x;
    const int cog = z >> 2, cls = z & 3;
    const int py = cls >> 1, px = cls & 1;
    const int y0 = (blockIdx.y >> 2) * 8;
    const int x0 = (blockIdx.y & 3) * 16;

    const int tid = threadIdx.x;
    const int lane = tid & 31;
    const int ww = tid >> 5;
    const int mwarp = ww & 1;
    const int nwarp = ww >> 1;
    const int gid = lane >> 2;
    const int tig = lane & 3;

    int nky = py ? 2 : 1, nkx = px ? 2 : 1;
    int dyA[2] = {0, 0};
    if (py) { dyA[0] = 1; dyA[1] = 0; }
    int dxA[2] = {0, 0};
    if (px) { dxA[0] = 1; dxA[1] = 0; }
    const int ntaps = nky * nkx;
    int tdy[4], tdx[4];
    for (int a = 0; a < nky; a++)
        for (int e = 0; e < nkx; e++) {
            int ta = a * nkx + e;
            tdy[ta] = dyA[a];
            tdx[ta] = dxA[e];
        }

    __shared__ uint4 s_w4[2][768];
    __shared__ unsigned s_ibuf[2][1344];
    const unsigned w_sa = (unsigned)__cvta_generic_to_shared(s_w4);
    const unsigned i_sa = (unsigned)__cvta_generic_to_shared(s_ibuf);

    float acc[2][8][4];
#pragma unroll
    for (int mt = 0; mt < 2; mt++)
#pragma unroll
        for (int j = 0; j < 8; j++)
#pragma unroll
            for (int q = 0; q < 4; q++) acc[mt][j][q] = 0.f;

    const float* inb = in + (size_t)b * 128 * 4096;
    const int nw4 = ntaps * 192;

    auto stage = [&](int cc, int buf) {
        unsigned ib = i_sa + buf * 5376;
        for (int idx = tid; idx < 8 * 153; idx += 128) {
            int c = idx / 153, r = idx - c * 153;
            int rr = r / 17, cx = r - rr * 17;
            int gy = y0 + rr, gx = x0 + cx;
            bool ok = (gy < 64 && gx < 64);
            const float* src = ok ? &inb[((size_t)(cc * 8 + c) * 64 + gy) * 64 + gx] : inb;
            cp_async4_p(ib + (c * 168 + rr * 17 + cx) * 4, src, ok);
        }
        unsigned wb = w_sa + buf * 12288;
        const uint4* wsrc =
            (const uint4*)(g_w4t + (size_t)(((cog * 4 + cls) * 16 + cc) * 4) * 768);
        for (int i = tid; i < nw4; i += 128) cp_async16(wb + i * 16, wsrc + i);
    };

    stage(0, 0);
    CP_COMMIT();

    for (int cc = 0; cc < 16; cc++) {
        __syncthreads();
        if (cc + 1 < 16) {
            stage(cc + 1, (cc + 1) & 1);
            CP_COMMIT();
            CP_WAIT1();
        } else {
            CP_WAIT0();
        }
        __syncthreads();
        const unsigned* s_in = s_ibuf[cc & 1];
        const unsigned* s_w = (const unsigned*)s_w4[cc & 1];

        for (int ta = 0; ta < ntaps; ta++) {
            unsigned a[2][4];
#pragma unroll
            for (int mt = 0; mt < 2; mt++) {
                int mrow = mwarp * 32 + mt * 16 + gid;
                a[mt][0] = s_w[ta * 768 + mrow * 12 + tig];
                a[mt][1] = s_w[ta * 768 + (mrow + 8) * 12 + tig];
                a[mt][2] = s_w[ta * 768 + mrow * 12 + tig + 4];
                a[mt][3] = s_w[ta * 768 + (mrow + 8) * 12 + tig + 4];
            }
            int dy = tdy[ta], dx = tdx[ta];
#pragma unroll
            for (int j = 0; j < 8; j++) {
                int jj = nwarp * 8 + j;
                int hy = (jj >> 1) + dy;
                int hx = (jj & 1) * 8 + gid + dx;
                unsigned bf[2];
                bf[0] = s_in[tig * 168 + hy * 17 + hx];
                bf[1] = s_in[(tig + 4) * 168 + hy * 17 + hx];
                mma_tf32(acc[0][j], a[0], bf);
                mma_tf32(acc[1][j], a[1], bf);
            }
        }
    }

#pragma unroll
    for (int mt = 0; mt < 2; mt++) {
        int co0 = cog * 64 + mwarp * 32 + mt * 16 + gid;
        float bs0 = bias[co0];
        float bs1 = bias[co0 + 8];
#pragma unroll
        for (int j = 0; j < 8; j++) {
            int jj = nwarp * 8 + j;
            int yc = y0 + (jj >> 1);
            int xc = x0 + (jj & 1) * 8 + 2 * tig;
            int y = 2 * yc + py;
            int x = 2 * xc + px;
            size_t o0 = (((size_t)(b * 256 + co0)) * 128 + y) * 128 + x;
            size_t o1 = (((size_t)(b * 256 + co0 + 8)) * 128 + y) * 128 + x;
            out[o0] = acc[mt][j][0] + bs0;
            out[o0 + 2] = acc[mt][j][1] + bs0;
            out[o1] = acc[mt][j][2] + bs1;
            out[o1 + 2] = acc[mt][j][3] + bs1;
        }
    }
}

// ---------------------------------------------------------------------------
// conv5 via tf32 mma + fused pooling, cp.async DOUBLE-buffered in 48640 B
// static smem. Pool bins overlay dead halo buffers. grid (8, 128, NB).
// ---------------------------------------------------------------------------
__global__ __launch_bounds__(128) void k_conv5_mma(const float* __restrict__ in,
                                                   const float* __restrict__ bias) {
    const int b = blockIdx.z;
    const int cog = blockIdx.x;
    const int y0 = (blockIdx.y >> 3) * 8;
    const int x0 = (blockIdx.y & 7) * 16;

    const int tid = threadIdx.x;
    const int lane = tid & 31;
    const int ww = tid >> 5;
    const int mwarp = ww & 1;
    const int nwarp = ww >> 1;
    const int gid = lane >> 2;
    const int tig = lane & 3;

    __shared__ unsigned s_raw[12160];   // w[2][4608] + in[2][1472]
    unsigned* s_wb = s_raw;
    unsigned* s_ib = s_raw + 9216;
    const unsigned base_sa = (unsigned)__cvta_generic_to_shared(s_raw);
    const unsigned w_sa = base_sa;
    const unsigned i_sa = base_sa + 9216 * 4;

    float acc[2][8][4];
#pragma unroll
    for (int mt = 0; mt < 2; mt++)
#pragma unroll
        for (int j = 0; j < 8; j++)
#pragma unroll
            for (int q = 0; q < 4; q++) acc[mt][j][q] = 0.f;

    const float* inb = in + (size_t)b * 256 * 16384;

    auto stage = [&](int cc, int buf) {
        unsigned ib = i_sa + buf * 5888;
        const float* cbase = inb + (size_t)cc * 8 * 16384;
        for (int idx = tid; idx < 8 * 180; idx += 128) {
            int c = idx / 180, r = idx - c * 180;
            int yy = r / 18, xx = r - yy * 18;
            int gy = refl(y0 - 1 + yy, 128);
            int gx = refl(x0 - 1 + xx, 128);
            cp_async4(ib + (c * 184 + yy * 18 + xx) * 4, cbase + c * 16384 + gy * 128 + gx);
        }
        unsigned wb = w_sa + buf * 18432;
        const uint4* wsrc = (const uint4*)(g_w5t + (size_t)(cog * 32 + cc) * 4608);
#pragma unroll
        for (int i = 0; i < 9; i++)
            cp_async16(wb + (tid + i * 128) * 16, wsrc + tid + i * 128);
    };

    stage(0, 0);
    CP_COMMIT();

    for (int cc = 0; cc < 32; cc++) {
        __syncthreads();
        if (cc + 1 < 32) {
            stage(cc + 1, (cc + 1) & 1);
            CP_COMMIT();
            CP_WAIT1();
        } else {
            CP_WAIT0();
        }
        __syncthreads();
        const unsigned* s_in = s_ib + (cc & 1) * 1472;
        const unsigned* s_w = s_wb + (cc & 1) * 4608;

#pragma unroll
        for (int t = 0; t < 9; t++) {
            const int ky = t / 3, kx = t - ky * 3;
            unsigned a[2][4];
#pragma unroll
            for (int mt = 0; mt < 2; mt++) {
                int mrow = mwarp * 32 + mt * 16 + gid;
                a[mt][0] = s_w[mrow * 72 + tig * 9 + t];
                a[mt][1] = s_w[(mrow + 8) * 72 + tig * 9 + t];
                a[mt][2] = s_w[mrow * 72 + (tig + 4) * 9 + t];
                a[mt][3] = s_w[(mrow + 8) * 72 + (tig + 4) * 9 + t];
            }
            unsigned bcur[2], bnxt[2];
            {
                int jj = nwarp * 8;
                int hy = (jj >> 1) + ky;
                int hx = (jj & 1) * 8 + gid + kx;
                bcur[0] = s_in[tig * 184 + hy * 18 + hx];
                bcur[1] = s_in[(tig + 4) * 184 + hy * 18 + hx];
            }
#pragma unroll
            for (int j = 0; j < 8; j++) {
                if (j < 7) {
                    int jj = nwarp * 8 + j + 1;
                    int hy = (jj >> 1) + ky;
                    int hx = (jj & 1) * 8 + gid + kx;
                    bnxt[0] = s_in[tig * 184 + hy * 18 + hx];
                    bnxt[1] = s_in[(tig + 4) * 184 + hy * 18 + hx];
                }
                mma_tf32(acc[0][j], a[0], bcur);
                mma_tf32(acc[1][j], a[1], bcur);
                bcur[0] = bnxt[0];
                bcur[1] = bnxt[1];
            }
        }
    }

    // epilogue: pool bins overlay dead halo buffers
    __syncthreads();
    float* s_pool = (float*)(s_raw + 9216);
    for (int i = tid; i < NS * 65; i += 128) s_pool[i] = 0.f;
    __syncthreads();

    const int* labp = g_label + b * 16384;
#pragma unroll
    for (int j = 0; j < 8; j++) {
        int jj = nwarp * 8 + j;
        int ly = jj >> 1;
        int lx = (jj & 1) * 8 + 2 * tig;
        int lbase = (y0 + ly) * 128 + x0 + lx;
        int lab0 = labp[lbase];
        int lab1 = labp[lbase + 1];
#pragma unroll
        for (int mt = 0; mt < 2; mt++) {
            int cl0 = mwarp * 32 + mt * 16 + gid;
            int co0 = cog * 64 + cl0;
            float bs0 = bias[co0];
            float bs1 = bias[co0 + 8];
            float v00 = tanhf(acc[mt][j][0] + bs0);
            float v01 = tanhf(acc[mt][j][1] + bs0);
            float v10 = tanhf(acc[mt][j][2] + bs1);
            float v11 = tanhf(acc[mt][j][3] + bs1);
            atomicAdd(&s_pool[lab0 * 65 + cl0], v00);
            atomicAdd(&s_pool[lab1 * 65 + cl0], v01);
            atomicAdd(&s_pool[lab0 * 65 + cl0 + 8], v10);
            atomicAdd(&s_pool[lab1 * 65 + cl0 + 8], v11);
        }
    }
    __syncthreads();
    for (int i = tid; i < NS * 64; i += 128) {
        int s = i >> 6, co = i & 63;
        float v = s_pool[s * 65 + co];
        if (v != 0.f)
            atomicAdd(&g_sums[((size_t)b * NS + s) * 512 + cog * 64 + co], v);
    }
}

// ---------------------------------------------------------------------------
__global__ void k_label(const float* __restrict__ seg) {
    int b = blockIdx.y;
    int i = blockIdx.x * 256 + threadIdx.x;
    int h = i >> 7, wv = i & 127;
    const float* sp = seg + (size_t)b * NS * 65536 + (2 * h) * 256 + 2 * wv;
    int lab = 0;
#pragma unroll 1
    for (int s = 0; s < NS; s++) {
        float v = sp[(size_t)s * 65536];
        if (v > 0.f) lab = s;
    }
    g_label[b * 16384 + i] = lab;
    atomicAdd(&g_cnt[b * NS + lab], 1);
}

// ---------------------------------------------------------------------------
__global__ void k_final(float* __restrict__ out) {
    int idx = blockIdx.x * 256 + threadIdx.x;
    if (idx >= NB * NS * 512) return;
    int bs = idx >> 9;
    int cnt = g_cnt[bs];
    out[idx] = cnt > 0 ? g_sums[idx] / (float)cnt : 0.f;
}

// ---------------------------------------------------------------------------
extern "C" void kernel_launch(void* const* d_in, const int* in_sizes, int n_in,
                              void* d_out, int out_size) {
    const float* input  = (const float*)d_in[0];
    const float* segmap = (const float*)d_in[1];
    const float* w1 = (const float*)d_in[2];
    const float* b1 = (const float*)d_in[3];
    const float* w2 = (const float*)d_in[4];
    const float* b2 = (const float*)d_in[5];
    const float* w3 = (const float*)d_in[6];
    const float* b3 = (const float*)d_in[7];
    const float* w4 = (const float*)d_in[8];
    const float* b4 = (const float*)d_in[9];
    const float* w5 = (const float*)d_in[10];
    const float* b5 = (const float*)d_in[11];
    float* out = (float*)d_out;

    float* act1;  cudaGetSymbolAddress((void**)&act1, g_act1);
    float* act2;  cudaGetSymbolAddress((void**)&act2, g_act2);
    float* act3;  cudaGetSymbolAddress((void**)&act3, g_act3);
    float* act4;  cudaGetSymbolAddress((void**)&act4, g_act4);
    unsigned* w2t; cudaGetSymbolAddress((void**)&w2t, g_w2t);
    unsigned* w3t; cudaGetSymbolAddress((void**)&w3t, g_w3t);

    // init + all weight prep in one launch
    k_init_all<<<(PREP_TOT + 255) / 256, 256>>>(w2, w3, w5, w4);
    k_label<<<dim3(64, NB), 256>>>(segmap);

    // L1
    k_conv1<<<dim3(256, NB), 256>>>(input, w1, b1);
    k_in_lrelu<<<NB * 32, 256>>>(act1, 65536 / 4);
    // L2
    k_conv_s2_mma<32, 256><<<dim3(1, 128, NB), 128>>>(act1, w2t, b2, act2, 64);
    k_in_lrelu<<<NB * 64, 256>>>(act2, 16384 / 4);
    // L3
    k_conv_s2_mma<64, 128><<<dim3(2, 32, NB), 128>>>(act2, w3t, b3, act3, 128);
    k_in_lrelu<<<NB * 128, 256>>>(act3, 4096 / 4);
    // L4
    k_convT_mma<<<dim3(16, 32, NB), 128>>>(act3, b4, act4);
    k_in_lrelu<<<NB * 256, 256>>>(act4, 16384 / 4);
    // L5 + fused pooling
    k_conv5_mma<<<dim3(8, 128, NB), 128>>>(act4, b5);
    // finalize
    k_final<<<(NB * NS * 512 + 255) / 256, 256>>>(out);
}